// round 1
// baseline (speedup 1.0000x reference)
#include <cuda_runtime.h>
#include <math.h>

#define BB 32
#define CC 256
#define HH 96
#define WW 96
#define GG 2
#define KK 3
#define CR 64
#define NOUT (CC*GG)

// Scratch (no allocs allowed): pooled block-sums, final dyn weights, dyn bias
__device__ float g_pooled[BB*CC*9];
__device__ float g_weight[BB*CC*9];
__device__ float g_bias[BB*CC];

// ---------------------------------------------------------------------------
// Kernel 1: per-(b,c) 3x3 block sums over 96x96 image.
// Block = 288 threads (9 warps), warp w handles cell (w/3, w%3) = 32x32 block.
// Vectorized float4 loads; warp reduction.
// ---------------------------------------------------------------------------
__global__ void pool_kernel(const float* __restrict__ x) {
    int bc = blockIdx.x;                  // 0..8191
    int w = threadIdx.x >> 5;             // warp 0..8
    int lane = threadIdx.x & 31;
    int cy = w / 3, cx = w % 3;
    const float* base = x + (size_t)bc * (HH*WW) + cy * 32 * WW + cx * 32;
    float s = 0.f;
#pragma unroll
    for (int i = 0; i < 8; i++) {
        int f = lane + i * 32;            // 0..255 float4 slots (32 rows x 8)
        int row = f >> 3, c4 = f & 7;
        float4 v = *reinterpret_cast<const float4*>(base + row * WW + c4 * 4);
        s += v.x + v.y + v.z + v.w;
    }
#pragma unroll
    for (int o = 16; o; o >>= 1) s += __shfl_xor_sync(0xffffffffu, s, o);
    if (lane == 0) g_pooled[bc * 9 + w] = s;
}

// ---------------------------------------------------------------------------
// Kernel 2: proj (1x1 conv -> BN -> exact GELU -> 1x1 conv) + softmax over G
// for 10 "positions" per sample: p=0..8 are pooled cells, p=9 is GAP.
// Grid (10, B), block 256. Produces g_weight [B,C,9] and g_bias [B,C].
// ---------------------------------------------------------------------------
__global__ void proj_kernel(const float* __restrict__ dyn_weight,
                            const float* __restrict__ dyn_bias,
                            const float* __restrict__ w1,
                            const float* __restrict__ bn_gamma,
                            const float* __restrict__ bn_beta,
                            const float* __restrict__ bn_mean,
                            const float* __restrict__ bn_var,
                            const float* __restrict__ w2,
                            const float* __restrict__ b2) {
    int p = blockIdx.x;                   // 0..9
    int b = blockIdx.y;                   // 0..31
    int t = threadIdx.x;                  // 0..255, t == channel c
    __shared__ float sv[CC];
    __shared__ float sh[CR];

    const float* ps = g_pooled + (size_t)b * CC * 9;
    float val;
    if (p < 9) {
        val = ps[t * 9 + p] * (1.0f / 1024.0f);     // 32x32 block mean
    } else {
        float s = 0.f;
#pragma unroll
        for (int q = 0; q < 9; q++) s += ps[t * 9 + q];
        val = s * (1.0f / (HH * WW));               // global mean
    }
    sv[t] = val;
    __syncthreads();

    if (t < CR) {
        float acc = 0.f;
        const float* wr = w1 + t * CC;
#pragma unroll 8
        for (int k = 0; k < CC; k++) acc = fmaf(wr[k], sv[k], acc);
        float inv = bn_gamma[t] * rsqrtf(bn_var[t] + 1e-5f);
        float h = acc * inv + (bn_beta[t] - bn_mean[t] * inv);
        // exact GELU (approximate=False)
        h = 0.5f * h * (1.0f + erff(h * 0.70710678118654752f));
        sh[t] = h;
    }
    __syncthreads();

    int c = t;
    float s0 = b2[c], s1 = b2[CC + c];
    const float* w2a = w2 + (size_t)c * CR;
    const float* w2b = w2 + (size_t)(CC + c) * CR;
#pragma unroll 8
    for (int k = 0; k < CR; k++) {
        float hv = sh[k];
        s0 = fmaf(w2a[k], hv, s0);
        s1 = fmaf(w2b[k], hv, s1);
    }
    // softmax over G=2 (n = g*C + c)
    float m = fmaxf(s0, s1);
    float e0 = __expf(s0 - m), e1 = __expf(s1 - m);
    float r = 1.0f / (e0 + e1);
    float p0 = e0 * r, p1 = e1 * r;

    size_t bc = (size_t)b * CC + c;
    if (p < 9) {
        g_weight[bc * 9 + p] = p0 * dyn_weight[c * 9 + p]
                             + p1 * dyn_weight[(CC + c) * 9 + p];
    } else {
        g_bias[bc] = p0 * dyn_bias[c] + p1 * dyn_bias[CC + c];
    }
}

// ---------------------------------------------------------------------------
// Kernel 3: per-sample depthwise 3x3 conv (pad 1) + bias.
// Block = 96 threads handles one (b,c) image. Thread (tx,ty) owns a 4-wide
// (cols 4tx..4tx+3) x 24-tall (rows 24ty..) strip. Streams 26 input rows,
// 1x float4 + 2 halo scalars per row, rolling 3 float4 output accumulators.
// ---------------------------------------------------------------------------
__global__ void dwconv_kernel(const float* __restrict__ x,
                              float* __restrict__ y) {
    int bc = blockIdx.x;
    int t = threadIdx.x;                  // 0..95
    int tx = t % 24;
    int ty = t / 24;                      // 0..3
    const float* img = x + (size_t)bc * (HH*WW);
    float* outimg = y + (size_t)bc * (HH*WW);

    float w0 = g_weight[bc*9+0], w1_ = g_weight[bc*9+1], w2_ = g_weight[bc*9+2];
    float w3 = g_weight[bc*9+3], w4  = g_weight[bc*9+4], w5  = g_weight[bc*9+5];
    float w6 = g_weight[bc*9+6], w7  = g_weight[bc*9+7], w8  = g_weight[bc*9+8];
    float bv = g_bias[bc];

    int x0 = tx * 4;
    int r0 = ty * 24;

    float4 aA = make_float4(0.f,0.f,0.f,0.f);
    float4 aB = make_float4(0.f,0.f,0.f,0.f);
    float4 aC = make_float4(0.f,0.f,0.f,0.f);

#pragma unroll 2
    for (int yy = r0 - 1; yy <= r0 + 24; ++yy) {
        float l = 0.f, c0 = 0.f, c1 = 0.f, c2 = 0.f, c3 = 0.f, rr = 0.f;
        if (yy >= 0 && yy < HH) {
            const float* row = img + yy * WW + x0;
            float4 v = *reinterpret_cast<const float4*>(row);
            c0 = v.x; c1 = v.y; c2 = v.z; c3 = v.w;
            if (tx > 0)  l  = row[-1];
            if (tx < 23) rr = row[4];
        }
        // input row yy contributes: weight row 2 -> out row yy-1 (aA),
        // row 1 -> out row yy (aB), row 0 -> out row yy+1 (aC)
        aA.x = fmaf(l,  w6, fmaf(c0, w7, fmaf(c1, w8, aA.x)));
        aA.y = fmaf(c0, w6, fmaf(c1, w7, fmaf(c2, w8, aA.y)));
        aA.z = fmaf(c1, w6, fmaf(c2, w7, fmaf(c3, w8, aA.z)));
        aA.w = fmaf(c2, w6, fmaf(c3, w7, fmaf(rr, w8, aA.w)));

        aB.x = fmaf(l,  w3, fmaf(c0, w4, fmaf(c1, w5, aB.x)));
        aB.y = fmaf(c0, w3, fmaf(c1, w4, fmaf(c2, w5, aB.y)));
        aB.z = fmaf(c1, w3, fmaf(c2, w4, fmaf(c3, w5, aB.z)));
        aB.w = fmaf(c2, w3, fmaf(c3, w4, fmaf(rr, w5, aB.w)));

        aC.x = fmaf(l,  w0, fmaf(c0, w1_, fmaf(c1, w2_, aC.x)));
        aC.y = fmaf(c0, w0, fmaf(c1, w1_, fmaf(c2, w2_, aC.y)));
        aC.z = fmaf(c1, w0, fmaf(c2, w1_, fmaf(c3, w2_, aC.z)));
        aC.w = fmaf(c2, w0, fmaf(c3, w1_, fmaf(rr, w2_, aC.w)));

        int yo = yy - 1;
        if (yo >= r0 && yo < r0 + 24) {
            float4 o;
            o.x = aA.x + bv; o.y = aA.y + bv; o.z = aA.z + bv; o.w = aA.w + bv;
            *reinterpret_cast<float4*>(outimg + yo * WW + x0) = o;
        }
        aA = aB; aB = aC;
        aC = make_float4(0.f,0.f,0.f,0.f);
    }
}

extern "C" void kernel_launch(void* const* d_in, const int* in_sizes, int n_in,
                              void* d_out, int out_size) {
    const float* x          = (const float*)d_in[0];
    const float* dyn_weight = (const float*)d_in[1];
    const float* dyn_bias   = (const float*)d_in[2];
    const float* w1         = (const float*)d_in[3];
    const float* bn_gamma   = (const float*)d_in[4];
    const float* bn_beta    = (const float*)d_in[5];
    const float* bn_mean    = (const float*)d_in[6];
    const float* bn_var     = (const float*)d_in[7];
    const float* w2         = (const float*)d_in[8];
    const float* b2         = (const float*)d_in[9];
    float* out = (float*)d_out;

    pool_kernel<<<BB*CC, 288>>>(x);
    dim3 pg(10, BB);
    proj_kernel<<<pg, 256>>>(dyn_weight, dyn_bias, w1, bn_gamma, bn_beta,
                             bn_mean, bn_var, w2, b2);
    dwconv_kernel<<<BB*CC, 96>>>(x, out);
}

// round 2
// speedup vs baseline: 1.2515x; 1.2515x over previous
#include <cuda_runtime.h>
#include <math.h>

#define BB 32
#define CC 256
#define HH 96
#define WW 96
#define GG 2
#define KK 3
#define CR 64

// Scratch (no allocs allowed)
__device__ float g_pooled[BB*CC*9];
__device__ float g_weight[BB*CC*9];
__device__ float g_bias[BB*CC];

// ---------------------------------------------------------------------------
// Kernel 1: per-(b,c) 3x3 block sums over 96x96 image. (unchanged - at roofline)
// ---------------------------------------------------------------------------
__global__ void pool_kernel(const float* __restrict__ x) {
    int bc = blockIdx.x;
    int w = threadIdx.x >> 5;
    int lane = threadIdx.x & 31;
    int cy = w / 3, cx = w % 3;
    const float* base = x + (size_t)bc * (HH*WW) + cy * 32 * WW + cx * 32;
    float s = 0.f;
#pragma unroll
    for (int i = 0; i < 8; i++) {
        int f = lane + i * 32;
        int row = f >> 3, c4 = f & 7;
        float4 v = *reinterpret_cast<const float4*>(base + row * WW + c4 * 4);
        s += v.x + v.y + v.z + v.w;
    }
#pragma unroll
    for (int o = 16; o; o >>= 1) s += __shfl_xor_sync(0xffffffffu, s, o);
    if (lane == 0) g_pooled[bc * 9 + w] = s;
}

// ---------------------------------------------------------------------------
// Kernel 2: proj + softmax over G -> dyn weights/bias. (unchanged)
// ---------------------------------------------------------------------------
__global__ void proj_kernel(const float* __restrict__ dyn_weight,
                            const float* __restrict__ dyn_bias,
                            const float* __restrict__ w1,
                            const float* __restrict__ bn_gamma,
                            const float* __restrict__ bn_beta,
                            const float* __restrict__ bn_mean,
                            const float* __restrict__ bn_var,
                            const float* __restrict__ w2,
                            const float* __restrict__ b2) {
    int p = blockIdx.x;
    int b = blockIdx.y;
    int t = threadIdx.x;
    __shared__ float sv[CC];
    __shared__ float sh[CR];

    const float* ps = g_pooled + (size_t)b * CC * 9;
    float val;
    if (p < 9) {
        val = ps[t * 9 + p] * (1.0f / 1024.0f);
    } else {
        float s = 0.f;
#pragma unroll
        for (int q = 0; q < 9; q++) s += ps[t * 9 + q];
        val = s * (1.0f / (HH * WW));
    }
    sv[t] = val;
    __syncthreads();

    if (t < CR) {
        float acc = 0.f;
        const float* wr = w1 + t * CC;
#pragma unroll 8
        for (int k = 0; k < CC; k++) acc = fmaf(wr[k], sv[k], acc);
        float inv = bn_gamma[t] * rsqrtf(bn_var[t] + 1e-5f);
        float h = acc * inv + (bn_beta[t] - bn_mean[t] * inv);
        h = 0.5f * h * (1.0f + erff(h * 0.70710678118654752f));
        sh[t] = h;
    }
    __syncthreads();

    int c = t;
    float s0 = b2[c], s1 = b2[CC + c];
    const float* w2a = w2 + (size_t)c * CR;
    const float* w2b = w2 + (size_t)(CC + c) * CR;
#pragma unroll 8
    for (int k = 0; k < CR; k++) {
        float hv = sh[k];
        s0 = fmaf(w2a[k], hv, s0);
        s1 = fmaf(w2b[k], hv, s1);
    }
    float m = fmaxf(s0, s1);
    float e0 = __expf(s0 - m), e1 = __expf(s1 - m);
    float r = 1.0f / (e0 + e1);
    float p0 = e0 * r, p1 = e1 * r;

    size_t bc = (size_t)b * CC + c;
    if (p < 9) {
        g_weight[bc * 9 + p] = p0 * dyn_weight[c * 9 + p]
                             + p1 * dyn_weight[(CC + c) * 9 + p];
    } else {
        g_bias[bc] = p0 * dyn_bias[c] + p1 * dyn_bias[CC + c];
    }
}

// ---------------------------------------------------------------------------
// Kernel 3: smem-staged per-sample depthwise 3x3 conv + bias.
// One block (288 thr) per (b,c) image. Stage 96x96 into zero-padded smem:
//   98 rows x 104-float pitch, image at [r+1][4..99]. Halos zeroed.
// Coalesced float4 loads (8/thread, MLP=8). Compute: thread (tx,ty) owns
// 4 cols x 8 rows, rolling 3-row float4 accumulators, 3 LDS/row, no branches.
// ---------------------------------------------------------------------------
#define PITCH 104
__global__ __launch_bounds__(288) void dwconv_kernel(const float* __restrict__ x,
                                                     float* __restrict__ y) {
    __shared__ float tile[98 * PITCH];
    int bc = blockIdx.x;
    int t = threadIdx.x;                  // 0..287
    const float* img = x + (size_t)bc * (HH*WW);
    float* outimg = y + (size_t)bc * (HH*WW);

    // --- zero halos (rows 0 & 97 full; cols 3 & 100 for rows 1..96) ---
    float4 z4 = make_float4(0.f,0.f,0.f,0.f);
    if (t < 26) {
        *reinterpret_cast<float4*>(&tile[t * 4]) = z4;                 // row 0
    } else if (t < 52) {
        *reinterpret_cast<float4*>(&tile[97 * PITCH + (t - 26) * 4]) = z4; // row 97
    } else if (t < 148) {
        tile[(t - 51) * PITCH + 3] = 0.f;                              // left halo
    } else if (t < 244) {
        tile[(t - 147) * PITCH + 100] = 0.f;                           // right halo
    }

    // --- stage image: 2304 float4, 8 per thread, coalesced ---
#pragma unroll
    for (int i = 0; i < 8; i++) {
        int idx = t + i * 288;            // 0..2303
        int r = idx / 24, j = idx % 24;   // wait: idx/24 up to 95
        float4 v = *reinterpret_cast<const float4*>(img + r * WW + j * 4);
        *reinterpret_cast<float4*>(&tile[(r + 1) * PITCH + 4 + j * 4]) = v;
    }
    __syncthreads();

    // --- compute ---
    int tx = t % 24;                      // column group: cols 4tx..4tx+3
    int ty = t / 24;                      // row group 0..11: rows 8ty..8ty+7
    int x0 = tx * 4;
    int r0 = ty * 8;                      // first output row

    float w0 = g_weight[bc*9+0], w1_ = g_weight[bc*9+1], w2_ = g_weight[bc*9+2];
    float w3 = g_weight[bc*9+3], w4  = g_weight[bc*9+4], w5  = g_weight[bc*9+5];
    float w6 = g_weight[bc*9+6], w7  = g_weight[bc*9+7], w8  = g_weight[bc*9+8];
    float bv = g_bias[bc];

    float4 aA = make_float4(0.f,0.f,0.f,0.f);
    float4 aB = make_float4(0.f,0.f,0.f,0.f);
    float4 aC = make_float4(0.f,0.f,0.f,0.f);

    // smem rows r0 .. r0+9 correspond to image rows r0-1 .. r0+8
#pragma unroll
    for (int s = 0; s < 10; ++s) {
        const float* row = &tile[(r0 + s) * PITCH + 4 + x0];
        float4 v = *reinterpret_cast<const float4*>(row);
        float l = row[-1];
        float rr = row[4];
        float c0 = v.x, c1 = v.y, c2 = v.z, c3 = v.w;

        aA.x = fmaf(l,  w6, fmaf(c0, w7, fmaf(c1, w8, aA.x)));
        aA.y = fmaf(c0, w6, fmaf(c1, w7, fmaf(c2, w8, aA.y)));
        aA.z = fmaf(c1, w6, fmaf(c2, w7, fmaf(c3, w8, aA.z)));
        aA.w = fmaf(c2, w6, fmaf(c3, w7, fmaf(rr, w8, aA.w)));

        aB.x = fmaf(l,  w3, fmaf(c0, w4, fmaf(c1, w5, aB.x)));
        aB.y = fmaf(c0, w3, fmaf(c1, w4, fmaf(c2, w5, aB.y)));
        aB.z = fmaf(c1, w3, fmaf(c2, w4, fmaf(c3, w5, aB.z)));
        aB.w = fmaf(c2, w3, fmaf(c3, w4, fmaf(rr, w5, aB.w)));

        aC.x = fmaf(l,  w0, fmaf(c0, w1_, fmaf(c1, w2_, aC.x)));
        aC.y = fmaf(c0, w0, fmaf(c1, w1_, fmaf(c2, w2_, aC.y)));
        aC.z = fmaf(c1, w0, fmaf(c2, w1_, fmaf(c3, w2_, aC.z)));
        aC.w = fmaf(c2, w0, fmaf(c3, w1_, fmaf(rr, w2_, aC.w)));

        if (s >= 2) {
            int yo = r0 + s - 2;
            float4 o;
            o.x = aA.x + bv; o.y = aA.y + bv; o.z = aA.z + bv; o.w = aA.w + bv;
            *reinterpret_cast<float4*>(outimg + yo * WW + x0) = o;
        }
        aA = aB; aB = aC;
        aC = make_float4(0.f,0.f,0.f,0.f);
    }
}

extern "C" void kernel_launch(void* const* d_in, const int* in_sizes, int n_in,
                              void* d_out, int out_size) {
    const float* x          = (const float*)d_in[0];
    const float* dyn_weight = (const float*)d_in[1];
    const float* dyn_bias   = (const float*)d_in[2];
    const float* w1         = (const float*)d_in[3];
    const float* bn_gamma   = (const float*)d_in[4];
    const float* bn_beta    = (const float*)d_in[5];
    const float* bn_mean    = (const float*)d_in[6];
    const float* bn_var     = (const float*)d_in[7];
    const float* w2         = (const float*)d_in[8];
    const float* b2         = (const float*)d_in[9];
    float* out = (float*)d_out;

    pool_kernel<<<BB*CC, 288>>>(x);
    dim3 pg(10, BB);
    proj_kernel<<<pg, 256>>>(dyn_weight, dyn_bias, w1, bn_gamma, bn_beta,
                             bn_mean, bn_var, w2, b2);
    dwconv_kernel<<<BB*CC, 288>>>(x, out);
}

// round 3
// speedup vs baseline: 1.2729x; 1.0171x over previous
#include <cuda_runtime.h>
#include <math.h>

#define BB 32
#define CC 256
#define HH 96
#define WW 96
#define CR 64

// Scratch (no allocs allowed)
__device__ float g_pooled[BB*CC*9];
__device__ float g_weight[BB*9*CC];     // [b][p][c]
__device__ float g_bias[BB*CC];
__device__ float g_w1t[CC*CR];          // [k][o], BN inv folded
__device__ float g_w2t[CR*2*CC];        // [k][n]
__device__ float g_bnb[CR];             // beta - mean*inv
__device__ float g_dwt[2*9*CC];         // [g][p][c]

// ---------------------------------------------------------------------------
// Kernel 0: prep — transposes + BN fold. 32768 threads, one-shot.
// ---------------------------------------------------------------------------
__global__ void prep_kernel(const float* __restrict__ w1,
                            const float* __restrict__ bn_gamma,
                            const float* __restrict__ bn_beta,
                            const float* __restrict__ bn_mean,
                            const float* __restrict__ bn_var,
                            const float* __restrict__ w2,
                            const float* __restrict__ dyn_weight) {
    int idx = blockIdx.x * 256 + threadIdx.x;
    if (idx < CC*CR) {                       // w1T with inv folded
        int k = idx >> 6, o = idx & 63;
        float inv = bn_gamma[o] * rsqrtf(bn_var[o] + 1e-5f);
        g_w1t[idx] = w1[o * CC + k] * inv;
    }
    if (idx < CR*2*CC) {                     // w2T
        int k = idx >> 9, n = idx & 511;
        g_w2t[idx] = w2[n * CR + k];
    }
    if (idx < 2*9*CC) {                      // dyn_weight -> [g][p][c]
        int g = idx / (9*CC);
        int rem = idx - g * 9 * CC;
        int p = rem >> 8, c = rem & 255;
        g_dwt[idx] = dyn_weight[(g * CC + c) * 9 + p];
    }
    if (idx < CR) {
        float inv = bn_gamma[idx] * rsqrtf(bn_var[idx] + 1e-5f);
        g_bnb[idx] = bn_beta[idx] - bn_mean[idx] * inv;
    }
}

// ---------------------------------------------------------------------------
// Kernel 1: per-(b,c) 3x3 block sums over 96x96 image. (at roofline)
// ---------------------------------------------------------------------------
__global__ void pool_kernel(const float* __restrict__ x) {
    int bc = blockIdx.x;
    int w = threadIdx.x >> 5;
    int lane = threadIdx.x & 31;
    int cy = w / 3, cx = w % 3;
    const float* base = x + (size_t)bc * (HH*WW) + cy * 32 * WW + cx * 32;
    float s = 0.f;
#pragma unroll
    for (int i = 0; i < 8; i++) {
        int f = lane + i * 32;
        int row = f >> 3, c4 = f & 7;
        float4 v = *reinterpret_cast<const float4*>(base + row * WW + c4 * 4);
        s += v.x + v.y + v.z + v.w;
    }
#pragma unroll
    for (int o = 16; o; o >>= 1) s += __shfl_xor_sync(0xffffffffu, s, o);
    if (lane == 0) g_pooled[bc * 9 + w] = s;
}

// ---------------------------------------------------------------------------
// Kernel 2 v2: one block per sample. All loads coalesced via transposed
// weights; activations broadcast from smem. 10 positions per block.
// ---------------------------------------------------------------------------
__global__ __launch_bounds__(256) void proj_kernel(const float* __restrict__ dyn_bias,
                                                   const float* __restrict__ b2) {
    __shared__ float raw[CC*9];      // g_pooled copy [c][p]
    __shared__ float sv[10*CC];      // [p][c] means
    __shared__ float sh[10*CR];      // [p][o] hidden
    int b = blockIdx.x;
    int t = threadIdx.x;

#pragma unroll
    for (int i = 0; i < 9; i++)
        raw[t + i * 256] = g_pooled[b * (CC*9) + t + i * 256];
    __syncthreads();

    {   // c = t
        float s = 0.f, vals[9];
#pragma unroll
        for (int p = 0; p < 9; p++) { vals[p] = raw[t * 9 + p]; s += vals[p]; }
#pragma unroll
        for (int p = 0; p < 9; p++) sv[p * CC + t] = vals[p] * (1.0f / 1024.0f);
        sv[9 * CC + t] = s * (1.0f / (HH*WW));
    }
    __syncthreads();

    // GEMM1: 640 items (p,o); w1T reads coalesced (consecutive o per lane)
#pragma unroll
    for (int i = 0; i < 3; i++) {
        int item = t + i * 256;
        if (item < 640) {
            int p = item >> 6, o = item & 63;
            const float* v = sv + p * CC;
            float acc = 0.f;
#pragma unroll 8
            for (int k = 0; k < CC; k++) acc = fmaf(g_w1t[k * CR + o], v[k], acc);
            float h = acc + g_bnb[o];
            h = 0.5f * h * (1.0f + erff(h * 0.70710678118654752f));
            sh[item] = h;
        }
    }
    __syncthreads();

    // GEMM2 + softmax: 2560 items (p,c); w2T reads coalesced
#pragma unroll
    for (int i = 0; i < 10; i++) {
        int item = t + i * 256;
        int p = item >> 8, c = item & 255;
        const float* hv = sh + p * CR;
        float a0 = b2[c], a1 = b2[CC + c];
#pragma unroll 8
        for (int k = 0; k < CR; k++) {
            float h = hv[k];
            a0 = fmaf(g_w2t[k * 512 + c], h, a0);
            a1 = fmaf(g_w2t[k * 512 + CC + c], h, a1);
        }
        float m = fmaxf(a0, a1);
        float e0 = __expf(a0 - m), e1 = __expf(a1 - m);
        float r = 1.0f / (e0 + e1);
        float p0 = e0 * r, p1 = e1 * r;
        if (p < 9) {
            g_weight[(b * 9 + p) * CC + c] = p0 * g_dwt[p * CC + c]
                                           + p1 * g_dwt[(9 + p) * CC + c];
        } else {
            g_bias[b * CC + c] = p0 * dyn_bias[c] + p1 * dyn_bias[CC + c];
        }
    }
}

// ---------------------------------------------------------------------------
// Kernel 3: smem-staged per-sample depthwise 3x3 conv + bias.
// ---------------------------------------------------------------------------
#define PITCH 104
__global__ __launch_bounds__(288) void dwconv_kernel(const float* __restrict__ x,
                                                     float* __restrict__ y) {
    __shared__ float tile[98 * PITCH];
    int bc = blockIdx.x;
    int t = threadIdx.x;
    const float* img = x + (size_t)bc * (HH*WW);
    float* outimg = y + (size_t)bc * (HH*WW);

    float4 z4 = make_float4(0.f,0.f,0.f,0.f);
    if (t < 26) {
        *reinterpret_cast<float4*>(&tile[t * 4]) = z4;
    } else if (t < 52) {
        *reinterpret_cast<float4*>(&tile[97 * PITCH + (t - 26) * 4]) = z4;
    } else if (t < 148) {
        tile[(t - 51) * PITCH + 3] = 0.f;
    } else if (t < 244) {
        tile[(t - 147) * PITCH + 100] = 0.f;
    }

#pragma unroll
    for (int i = 0; i < 8; i++) {
        int idx = t + i * 288;
        int r = idx / 24, j = idx % 24;
        float4 v = *reinterpret_cast<const float4*>(img + r * WW + j * 4);
        *reinterpret_cast<float4*>(&tile[(r + 1) * PITCH + 4 + j * 4]) = v;
    }

    int b = bc >> 8, c = bc & 255;
    float w0 = g_weight[(b*9+0)*CC+c], w1_ = g_weight[(b*9+1)*CC+c], w2_ = g_weight[(b*9+2)*CC+c];
    float w3 = g_weight[(b*9+3)*CC+c], w4  = g_weight[(b*9+4)*CC+c], w5  = g_weight[(b*9+5)*CC+c];
    float w6 = g_weight[(b*9+6)*CC+c], w7  = g_weight[(b*9+7)*CC+c], w8  = g_weight[(b*9+8)*CC+c];
    float bv = g_bias[bc];
    __syncthreads();

    int tx = t % 24;
    int ty = t / 24;
    int x0 = tx * 4;
    int r0 = ty * 8;

    float4 aA = make_float4(0.f,0.f,0.f,0.f);
    float4 aB = make_float4(0.f,0.f,0.f,0.f);
    float4 aC = make_float4(0.f,0.f,0.f,0.f);

#pragma unroll
    for (int s = 0; s < 10; ++s) {
        const float* row = &tile[(r0 + s) * PITCH + 4 + x0];
        float4 v = *reinterpret_cast<const float4*>(row);
        float l = row[-1];
        float rr = row[4];
        float c0 = v.x, c1 = v.y, c2 = v.z, c3 = v.w;

        aA.x = fmaf(l,  w6, fmaf(c0, w7, fmaf(c1, w8, aA.x)));
        aA.y = fmaf(c0, w6, fmaf(c1, w7, fmaf(c2, w8, aA.y)));
        aA.z = fmaf(c1, w6, fmaf(c2, w7, fmaf(c3, w8, aA.z)));
        aA.w = fmaf(c2, w6, fmaf(c3, w7, fmaf(rr, w8, aA.w)));

        aB.x = fmaf(l,  w3, fmaf(c0, w4, fmaf(c1, w5, aB.x)));
        aB.y = fmaf(c0, w3, fmaf(c1, w4, fmaf(c2, w5, aB.y)));
        aB.z = fmaf(c1, w3, fmaf(c2, w4, fmaf(c3, w5, aB.z)));
        aB.w = fmaf(c2, w3, fmaf(c3, w4, fmaf(rr, w5, aB.w)));

        aC.x = fmaf(l,  w0, fmaf(c0, w1_, fmaf(c1, w2_, aC.x)));
        aC.y = fmaf(c0, w0, fmaf(c1, w1_, fmaf(c2, w2_, aC.y)));
        aC.z = fmaf(c1, w0, fmaf(c2, w1_, fmaf(c3, w2_, aC.z)));
        aC.w = fmaf(c2, w0, fmaf(c3, w1_, fmaf(rr, w2_, aC.w)));

        if (s >= 2) {
            int yo = r0 + s - 2;
            float4 o;
            o.x = aA.x + bv; o.y = aA.y + bv; o.z = aA.z + bv; o.w = aA.w + bv;
            __stcs(reinterpret_cast<float4*>(outimg + yo * WW + x0), o);
        }
        aA = aB; aB = aC;
        aC = make_float4(0.f,0.f,0.f,0.f);
    }
}

extern "C" void kernel_launch(void* const* d_in, const int* in_sizes, int n_in,
                              void* d_out, int out_size) {
    const float* x          = (const float*)d_in[0];
    const float* dyn_weight = (const float*)d_in[1];
    const float* dyn_bias   = (const float*)d_in[2];
    const float* w1         = (const float*)d_in[3];
    const float* bn_gamma   = (const float*)d_in[4];
    const float* bn_beta    = (const float*)d_in[5];
    const float* bn_mean    = (const float*)d_in[6];
    const float* bn_var     = (const float*)d_in[7];
    const float* w2         = (const float*)d_in[8];
    const float* b2         = (const float*)d_in[9];
    float* out = (float*)d_out;

    prep_kernel<<<128, 256>>>(w1, bn_gamma, bn_beta, bn_mean, bn_var, w2, dyn_weight);
    pool_kernel<<<BB*CC, 288>>>(x);
    proj_kernel<<<BB, 256>>>(dyn_bias, b2);
    dwconv_kernel<<<BB*CC, 288>>>(x, out);
}

// round 4
// speedup vs baseline: 1.7057x; 1.3400x over previous
#include <cuda_runtime.h>
#include <math.h>

#define BB 32
#define CC 256
#define HH 96
#define WW 96
#define CR 64

// Scratch (no allocs allowed)
__device__ float g_pooled[BB*9*CC];     // [b][p][c]  (block sums)
__device__ float g_hidden[BB*10*CR];    // [b][p][o]  (post-GELU)
__device__ float g_weight[BB*9*CC];     // [b][p][c]
__device__ float g_bias[BB*CC];
__device__ float g_w1t[CC*CR];          // [k][o], BN inv folded
__device__ float g_w2t[CR*2*CC];        // [k][n]
__device__ float g_bnb[CR];             // beta - mean*inv
__device__ float g_dwt[2*9*CC];         // [g][p][c]

// ---------------------------------------------------------------------------
// Kernel 0: prep — transposes + BN fold.
// ---------------------------------------------------------------------------
__global__ void prep_kernel(const float* __restrict__ w1,
                            const float* __restrict__ bn_gamma,
                            const float* __restrict__ bn_beta,
                            const float* __restrict__ bn_mean,
                            const float* __restrict__ bn_var,
                            const float* __restrict__ w2,
                            const float* __restrict__ dyn_weight) {
    int idx = blockIdx.x * 256 + threadIdx.x;
    if (idx < CC*CR) {
        int k = idx >> 6, o = idx & 63;
        float inv = bn_gamma[o] * rsqrtf(bn_var[o] + 1e-5f);
        g_w1t[idx] = w1[o * CC + k] * inv;
    }
    if (idx < CR*2*CC) {
        int k = idx >> 9, n = idx & 511;
        g_w2t[idx] = w2[n * CR + k];
    }
    if (idx < 2*9*CC) {
        int g = idx / (9*CC);
        int rem = idx - g * 9 * CC;
        int p = rem >> 8, c = rem & 255;
        g_dwt[idx] = dyn_weight[(g * CC + c) * 9 + p];
    }
    if (idx < CR) {
        float inv = bn_gamma[idx] * rsqrtf(bn_var[idx] + 1e-5f);
        g_bnb[idx] = bn_beta[idx] - bn_mean[idx] * inv;
    }
}

// ---------------------------------------------------------------------------
// Kernel 1: per-(b,c) 3x3 block sums. Writes [b][p][c].
// ---------------------------------------------------------------------------
__global__ void pool_kernel(const float* __restrict__ x) {
    int bc = blockIdx.x;
    int w = threadIdx.x >> 5;
    int lane = threadIdx.x & 31;
    int cy = w / 3, cx = w % 3;
    const float* base = x + (size_t)bc * (HH*WW) + cy * 32 * WW + cx * 32;
    float s = 0.f;
#pragma unroll
    for (int i = 0; i < 8; i++) {
        int f = lane + i * 32;
        int row = f >> 3, c4 = f & 7;
        float4 v = __ldcs(reinterpret_cast<const float4*>(base + row * WW + c4 * 4));
        s += v.x + v.y + v.z + v.w;
    }
#pragma unroll
    for (int o = 16; o; o >>= 1) s += __shfl_xor_sync(0xffffffffu, s, o);
    if (lane == 0)
        g_pooled[((bc >> 8) * 9 + w) * CC + (bc & 255)] = s;
}

// ---------------------------------------------------------------------------
// Kernel 2a: GEMM1 + BN + exact GELU. Grid (10, B), 256 thr, 4-way k-split.
// ---------------------------------------------------------------------------
__global__ __launch_bounds__(256) void proj1_kernel() {
    __shared__ float v[CC];
    __shared__ float part[256];
    int p = blockIdx.x;                   // 0..9
    int b = blockIdx.y;
    int t = threadIdx.x;

    float val;
    if (p < 9) {
        val = g_pooled[(b * 9 + p) * CC + t] * (1.0f / 1024.0f);
    } else {
        float s = 0.f;
#pragma unroll
        for (int q = 0; q < 9; q++) s += g_pooled[(b * 9 + q) * CC + t];
        val = s * (1.0f / (HH * WW));
    }
    v[t] = val;
    __syncthreads();

    int o = t & 63, slice = t >> 6;       // 4 slices of 64 k each
    const float* w1s = g_w1t + slice * 64 * CR + o;
    const float* vs = v + slice * 64;
    float acc = 0.f;
#pragma unroll 8
    for (int k = 0; k < 64; k++) acc = fmaf(w1s[k * CR], vs[k], acc);
    part[t] = acc;
    __syncthreads();

    if (t < CR) {
        float h = part[t] + part[t + 64] + part[t + 128] + part[t + 192] + g_bnb[t];
        h = 0.5f * h * (1.0f + erff(h * 0.70710678118654752f));
        g_hidden[(b * 10 + p) * CR + t] = h;
    }
}

// ---------------------------------------------------------------------------
// Kernel 2b: GEMM2 + softmax over G + mix with banks. Grid (10, B), 256 thr.
// ---------------------------------------------------------------------------
__global__ __launch_bounds__(256) void proj2_kernel(const float* __restrict__ dyn_bias,
                                                    const float* __restrict__ b2) {
    __shared__ float h[CR];
    int p = blockIdx.x;
    int b = blockIdx.y;
    int c = threadIdx.x;

    if (c < CR) h[c] = g_hidden[(b * 10 + p) * CR + c];
    __syncthreads();

    float a0 = b2[c], a1 = b2[CC + c];
#pragma unroll 8
    for (int k = 0; k < CR; k++) {
        float hv = h[k];
        a0 = fmaf(g_w2t[k * 512 + c], hv, a0);
        a1 = fmaf(g_w2t[k * 512 + CC + c], hv, a1);
    }
    float m = fmaxf(a0, a1);
    float e0 = __expf(a0 - m), e1 = __expf(a1 - m);
    float r = 1.0f / (e0 + e1);
    float p0 = e0 * r, p1 = e1 * r;

    if (p < 9) {
        g_weight[(b * 9 + p) * CC + c] = p0 * g_dwt[p * CC + c]
                                       + p1 * g_dwt[(9 + p) * CC + c];
    } else {
        g_bias[b * CC + c] = p0 * dyn_bias[c] + p1 * dyn_bias[CC + c];
    }
}

// ---------------------------------------------------------------------------
// Kernel 3: smem-staged per-sample depthwise 3x3 conv + bias.
// ---------------------------------------------------------------------------
#define PITCH 104
__global__ __launch_bounds__(288, 5) void dwconv_kernel(const float* __restrict__ x,
                                                        float* __restrict__ y) {
    __shared__ float tile[98 * PITCH];
    int bc = blockIdx.x;
    int t = threadIdx.x;
    const float* img = x + (size_t)bc * (HH*WW);
    float* outimg = y + (size_t)bc * (HH*WW);

    float4 z4 = make_float4(0.f,0.f,0.f,0.f);
    if (t < 26) {
        *reinterpret_cast<float4*>(&tile[t * 4]) = z4;
    } else if (t < 52) {
        *reinterpret_cast<float4*>(&tile[97 * PITCH + (t - 26) * 4]) = z4;
    } else if (t < 148) {
        tile[(t - 51) * PITCH + 3] = 0.f;
    } else if (t < 244) {
        tile[(t - 147) * PITCH + 100] = 0.f;
    }

#pragma unroll
    for (int i = 0; i < 8; i++) {
        int idx = t + i * 288;
        int r = idx / 24, j = idx % 24;
        float4 v = __ldcs(reinterpret_cast<const float4*>(img + r * WW + j * 4));
        *reinterpret_cast<float4*>(&tile[(r + 1) * PITCH + 4 + j * 4]) = v;
    }

    int b = bc >> 8, c = bc & 255;
    float w0 = g_weight[(b*9+0)*CC+c], w1_ = g_weight[(b*9+1)*CC+c], w2_ = g_weight[(b*9+2)*CC+c];
    float w3 = g_weight[(b*9+3)*CC+c], w4  = g_weight[(b*9+4)*CC+c], w5  = g_weight[(b*9+5)*CC+c];
    float w6 = g_weight[(b*9+6)*CC+c], w7  = g_weight[(b*9+7)*CC+c], w8  = g_weight[(b*9+8)*CC+c];
    float bv = g_bias[bc];
    __syncthreads();

    int tx = t % 24;
    int ty = t / 24;
    int x0 = tx * 4;
    int r0 = ty * 8;

    float4 aA = make_float4(0.f,0.f,0.f,0.f);
    float4 aB = make_float4(0.f,0.f,0.f,0.f);
    float4 aC = make_float4(0.f,0.f,0.f,0.f);

#pragma unroll
    for (int s = 0; s < 10; ++s) {
        const float* row = &tile[(r0 + s) * PITCH + 4 + x0];
        float4 v = *reinterpret_cast<const float4*>(row);
        float l = row[-1];
        float rr = row[4];
        float c0 = v.x, c1 = v.y, c2 = v.z, c3 = v.w;

        aA.x = fmaf(l,  w6, fmaf(c0, w7, fmaf(c1, w8, aA.x)));
        aA.y = fmaf(c0, w6, fmaf(c1, w7, fmaf(c2, w8, aA.y)));
        aA.z = fmaf(c1, w6, fmaf(c2, w7, fmaf(c3, w8, aA.z)));
        aA.w = fmaf(c2, w6, fmaf(c3, w7, fmaf(rr, w8, aA.w)));

        aB.x = fmaf(l,  w3, fmaf(c0, w4, fmaf(c1, w5, aB.x)));
        aB.y = fmaf(c0, w3, fmaf(c1, w4, fmaf(c2, w5, aB.y)));
        aB.z = fmaf(c1, w3, fmaf(c2, w4, fmaf(c3, w5, aB.z)));
        aB.w = fmaf(c2, w3, fmaf(c3, w4, fmaf(rr, w5, aB.w)));

        aC.x = fmaf(l,  w0, fmaf(c0, w1_, fmaf(c1, w2_, aC.x)));
        aC.y = fmaf(c0, w0, fmaf(c1, w1_, fmaf(c2, w2_, aC.y)));
        aC.z = fmaf(c1, w0, fmaf(c2, w1_, fmaf(c3, w2_, aC.z)));
        aC.w = fmaf(c2, w0, fmaf(c3, w1_, fmaf(rr, w2_, aC.w)));

        if (s >= 2) {
            int yo = r0 + s - 2;
            float4 o;
            o.x = aA.x + bv; o.y = aA.y + bv; o.z = aA.z + bv; o.w = aA.w + bv;
            __stcs(reinterpret_cast<float4*>(outimg + yo * WW + x0), o);
        }
        aA = aB; aB = aC;
        aC = make_float4(0.f,0.f,0.f,0.f);
    }
}

extern "C" void kernel_launch(void* const* d_in, const int* in_sizes, int n_in,
                              void* d_out, int out_size) {
    const float* x          = (const float*)d_in[0];
    const float* dyn_weight = (const float*)d_in[1];
    const float* dyn_bias   = (const float*)d_in[2];
    const float* w1         = (const float*)d_in[3];
    const float* bn_gamma   = (const float*)d_in[4];
    const float* bn_beta    = (const float*)d_in[5];
    const float* bn_mean    = (const float*)d_in[6];
    const float* bn_var     = (const float*)d_in[7];
    const float* w2         = (const float*)d_in[8];
    const float* b2         = (const float*)d_in[9];
    float* out = (float*)d_out;

    prep_kernel<<<128, 256>>>(w1, bn_gamma, bn_beta, bn_mean, bn_var, w2, dyn_weight);
    pool_kernel<<<BB*CC, 288>>>(x);
    dim3 pg(10, BB);
    proj1_kernel<<<pg, 256>>>();
    proj2_kernel<<<pg, 256>>>(dyn_bias, b2);
    dwconv_kernel<<<BB*CC, 288>>>(x, out);
}

// round 5
// speedup vs baseline: 1.7250x; 1.0113x over previous
#include <cuda_runtime.h>
#include <math.h>

#define BB 32
#define CC 256
#define HH 96
#define WW 96
#define CR 64

// Scratch (no allocs allowed)
__device__ float g_pooled[BB*9*CC];     // [b][p][c]  (block sums)
__device__ float g_weight[BB*9*CC];     // [b][p][c]
__device__ float g_bias[BB*CC];
__device__ float g_w1t[CC*CR];          // [k][o], BN inv folded
__device__ float g_w2t[CR*2*CC];        // [k][n]
__device__ float g_bnb[CR];             // beta - mean*inv
__device__ float g_dwt[2*9*CC];         // [g][p][c]

// ---------------------------------------------------------------------------
// Kernel 1: per-(b,c) 3x3 block sums. Writes [b][p][c].
// Blocks 0..113 additionally perform the prep (transpose + BN fold) work,
// hidden under the DRAM-bound pooling pass.
// ---------------------------------------------------------------------------
__global__ void pool_kernel(const float* __restrict__ x,
                            const float* __restrict__ w1,
                            const float* __restrict__ bn_gamma,
                            const float* __restrict__ bn_beta,
                            const float* __restrict__ bn_mean,
                            const float* __restrict__ bn_var,
                            const float* __restrict__ w2,
                            const float* __restrict__ dyn_weight) {
    int bc = blockIdx.x;

    if (bc < 114) {                       // prep work: idx 0..32831 covers 32768
        int idx = bc * 288 + threadIdx.x;
        if (idx < CC*CR) {
            int k = idx >> 6, o = idx & 63;
            float inv = bn_gamma[o] * rsqrtf(bn_var[o] + 1e-5f);
            g_w1t[idx] = w1[o * CC + k] * inv;
        }
        if (idx < CR*2*CC) {
            int k = idx >> 9, n = idx & 511;
            g_w2t[idx] = w2[n * CR + k];
        }
        if (idx < 2*9*CC) {
            int g = idx / (9*CC);
            int rem = idx - g * 9 * CC;
            int p = rem >> 8, c = rem & 255;
            g_dwt[idx] = dyn_weight[(g * CC + c) * 9 + p];
        }
        if (idx < CR) {
            float inv = bn_gamma[idx] * rsqrtf(bn_var[idx] + 1e-5f);
            g_bnb[idx] = bn_beta[idx] - bn_mean[idx] * inv;
        }
    }

    int w = threadIdx.x >> 5;
    int lane = threadIdx.x & 31;
    int cy = w / 3, cx = w % 3;
    const float* base = x + (size_t)bc * (HH*WW) + cy * 32 * WW + cx * 32;
    float s = 0.f;
#pragma unroll
    for (int i = 0; i < 8; i++) {
        int f = lane + i * 32;
        int row = f >> 3, c4 = f & 7;
        float4 v = __ldcs(reinterpret_cast<const float4*>(base + row * WW + c4 * 4));
        s += v.x + v.y + v.z + v.w;
    }
#pragma unroll
    for (int o = 16; o; o >>= 1) s += __shfl_xor_sync(0xffffffffu, s, o);
    if (lane == 0)
        g_pooled[((bc >> 8) * 9 + w) * CC + (bc & 255)] = s;
}

// ---------------------------------------------------------------------------
// Kernel 2: fused proj. Grid (5, B) = 160 blocks; block handles positions
// p and p+5 of sample b. GEMM1 4-way k-split; GEMM2 weight loads shared
// across the two positions.
// ---------------------------------------------------------------------------
__global__ __launch_bounds__(256) void projf_kernel(const float* __restrict__ dyn_bias,
                                                    const float* __restrict__ b2) {
    __shared__ float sv0[CC], sv1[CC];
    __shared__ float pa[2*256];
    __shared__ float sh0[CR], sh1[CR];
    int p = blockIdx.x;                   // 0..4
    int p2 = p + 5;                       // 5..9
    int b = blockIdx.y;
    int t = threadIdx.x;

    float v0 = g_pooled[(b * 9 + p) * CC + t] * (1.0f / 1024.0f);
    float v1;
    if (p2 < 9) {
        v1 = g_pooled[(b * 9 + p2) * CC + t] * (1.0f / 1024.0f);
    } else {
        float s = 0.f;
#pragma unroll
        for (int q = 0; q < 9; q++) s += g_pooled[(b * 9 + q) * CC + t];
        v1 = s * (1.0f / (HH * WW));
    }
    sv0[t] = v0; sv1[t] = v1;
    __syncthreads();

    int o = t & 63, slice = t >> 6;
    const float* w1s = g_w1t + slice * 64 * CR + o;
    const float* a0p = sv0 + slice * 64;
    const float* a1p = sv1 + slice * 64;
    float acc0 = 0.f, acc1 = 0.f;
#pragma unroll 8
    for (int k = 0; k < 64; k++) {
        float w = w1s[k * CR];
        acc0 = fmaf(w, a0p[k], acc0);
        acc1 = fmaf(w, a1p[k], acc1);
    }
    pa[t] = acc0; pa[256 + t] = acc1;
    __syncthreads();

    if (t < 128) {
        int pos = t >> 6, oo = t & 63;
        const float* pp = pa + pos * 256;
        float h = pp[oo] + pp[oo + 64] + pp[oo + 128] + pp[oo + 192] + g_bnb[oo];
        h = 0.5f * h * (1.0f + erff(h * 0.70710678118654752f));
        if (pos) sh1[oo] = h; else sh0[oo] = h;
    }
    __syncthreads();

    int c = t;
    float a0 = b2[c], a1 = b2[CC + c];
    float d0 = a0, d1 = a1;
#pragma unroll 8
    for (int k = 0; k < CR; k++) {
        float w_0 = g_w2t[k * 512 + c];
        float w_1 = g_w2t[k * 512 + CC + c];
        float h0 = sh0[k], h1 = sh1[k];
        a0 = fmaf(w_0, h0, a0); a1 = fmaf(w_1, h0, a1);
        d0 = fmaf(w_0, h1, d0); d1 = fmaf(w_1, h1, d1);
    }
    {   // position p (always a weight cell)
        float m = fmaxf(a0, a1);
        float e0 = __expf(a0 - m), e1 = __expf(a1 - m);
        float r = 1.0f / (e0 + e1);
        g_weight[(b * 9 + p) * CC + c] = e0 * r * g_dwt[p * CC + c]
                                       + e1 * r * g_dwt[(9 + p) * CC + c];
    }
    {   // position p2 (weight cell 5..8, or bias when p2==9)
        float m = fmaxf(d0, d1);
        float e0 = __expf(d0 - m), e1 = __expf(d1 - m);
        float r = 1.0f / (e0 + e1);
        if (p2 < 9) {
            g_weight[(b * 9 + p2) * CC + c] = e0 * r * g_dwt[p2 * CC + c]
                                            + e1 * r * g_dwt[(9 + p2) * CC + c];
        } else {
            g_bias[b * CC + c] = e0 * r * dyn_bias[c] + e1 * r * dyn_bias[CC + c];
        }
    }
}

// ---------------------------------------------------------------------------
// Kernel 3: smem-staged per-sample depthwise 3x3 conv + bias.
// ---------------------------------------------------------------------------
#define PITCH 104
__global__ __launch_bounds__(288, 5) void dwconv_kernel(const float* __restrict__ x,
                                                        float* __restrict__ y) {
    __shared__ float tile[98 * PITCH];
    int bc = blockIdx.x;
    int t = threadIdx.x;
    const float* img = x + (size_t)bc * (HH*WW);
    float* outimg = y + (size_t)bc * (HH*WW);

    float4 z4 = make_float4(0.f,0.f,0.f,0.f);
    if (t < 26) {
        *reinterpret_cast<float4*>(&tile[t * 4]) = z4;
    } else if (t < 52) {
        *reinterpret_cast<float4*>(&tile[97 * PITCH + (t - 26) * 4]) = z4;
    } else if (t < 148) {
        tile[(t - 51) * PITCH + 3] = 0.f;
    } else if (t < 244) {
        tile[(t - 147) * PITCH + 100] = 0.f;
    }

#pragma unroll
    for (int i = 0; i < 8; i++) {
        int idx = t + i * 288;
        int r = idx / 24, j = idx % 24;
        float4 v = __ldcs(reinterpret_cast<const float4*>(img + r * WW + j * 4));
        *reinterpret_cast<float4*>(&tile[(r + 1) * PITCH + 4 + j * 4]) = v;
    }

    int b = bc >> 8, c = bc & 255;
    float w0 = g_weight[(b*9+0)*CC+c], w1_ = g_weight[(b*9+1)*CC+c], w2_ = g_weight[(b*9+2)*CC+c];
    float w3 = g_weight[(b*9+3)*CC+c], w4  = g_weight[(b*9+4)*CC+c], w5  = g_weight[(b*9+5)*CC+c];
    float w6 = g_weight[(b*9+6)*CC+c], w7  = g_weight[(b*9+7)*CC+c], w8  = g_weight[(b*9+8)*CC+c];
    float bv = g_bias[bc];
    __syncthreads();

    int tx = t % 24;
    int ty = t / 24;
    int x0 = tx * 4;
    int r0 = ty * 8;

    float4 aA = make_float4(0.f,0.f,0.f,0.f);
    float4 aB = make_float4(0.f,0.f,0.f,0.f);
    float4 aC = make_float4(0.f,0.f,0.f,0.f);

#pragma unroll
    for (int s = 0; s < 10; ++s) {
        const float* row = &tile[(r0 + s) * PITCH + 4 + x0];
        float4 v = *reinterpret_cast<const float4*>(row);
        float l = row[-1];
        float rr = row[4];
        float c0 = v.x, c1 = v.y, c2 = v.z, c3 = v.w;

        aA.x = fmaf(l,  w6, fmaf(c0, w7, fmaf(c1, w8, aA.x)));
        aA.y = fmaf(c0, w6, fmaf(c1, w7, fmaf(c2, w8, aA.y)));
        aA.z = fmaf(c1, w6, fmaf(c2, w7, fmaf(c3, w8, aA.z)));
        aA.w = fmaf(c2, w6, fmaf(c3, w7, fmaf(rr, w8, aA.w)));

        aB.x = fmaf(l,  w3, fmaf(c0, w4, fmaf(c1, w5, aB.x)));
        aB.y = fmaf(c0, w3, fmaf(c1, w4, fmaf(c2, w5, aB.y)));
        aB.z = fmaf(c1, w3, fmaf(c2, w4, fmaf(c3, w5, aB.z)));
        aB.w = fmaf(c2, w3, fmaf(c3, w4, fmaf(rr, w5, aB.w)));

        aC.x = fmaf(l,  w0, fmaf(c0, w1_, fmaf(c1, w2_, aC.x)));
        aC.y = fmaf(c0, w0, fmaf(c1, w1_, fmaf(c2, w2_, aC.y)));
        aC.z = fmaf(c1, w0, fmaf(c2, w1_, fmaf(c3, w2_, aC.z)));
        aC.w = fmaf(c2, w0, fmaf(c3, w1_, fmaf(rr, w2_, aC.w)));

        if (s >= 2) {
            int yo = r0 + s - 2;
            float4 o;
            o.x = aA.x + bv; o.y = aA.y + bv; o.z = aA.z + bv; o.w = aA.w + bv;
            __stcs(reinterpret_cast<float4*>(outimg + yo * WW + x0), o);
        }
        aA = aB; aB = aC;
        aC = make_float4(0.f,0.f,0.f,0.f);
    }
}

extern "C" void kernel_launch(void* const* d_in, const int* in_sizes, int n_in,
                              void* d_out, int out_size) {
    const float* x          = (const float*)d_in[0];
    const float* dyn_weight = (const float*)d_in[1];
    const float* dyn_bias   = (const float*)d_in[2];
    const float* w1         = (const float*)d_in[3];
    const float* bn_gamma   = (const float*)d_in[4];
    const float* bn_beta    = (const float*)d_in[5];
    const float* bn_mean    = (const float*)d_in[6];
    const float* bn_var     = (const float*)d_in[7];
    const float* w2         = (const float*)d_in[8];
    const float* b2         = (const float*)d_in[9];
    float* out = (float*)d_out;

    pool_kernel<<<BB*CC, 288>>>(x, w1, bn_gamma, bn_beta, bn_mean, bn_var, w2, dyn_weight);
    dim3 pg(5, BB);
    projf_kernel<<<pg, 256>>>(dyn_bias, b2);
    dwconv_kernel<<<BB*CC, 288>>>(x, out);
}

// round 6
// speedup vs baseline: 1.8942x; 1.0981x over previous
#include <cuda_runtime.h>
#include <math.h>

#define BB 32
#define CC 256
#define HH 96
#define WW 96
#define CR 64

// Scratch (no allocs allowed)
__device__ float g_pooled[BB*9*CC];     // [b][p][c]  (block sums)
__device__ float g_weight[BB*9*CC];     // [b][p][c]
__device__ float g_bias[BB*CC];
__device__ float g_w1t[CC*CR];          // [k][o], BN inv folded
__device__ float g_w2t[CR*2*CC];        // [k][n]
__device__ float g_bnb[CR];             // beta - mean*inv
__device__ float g_dwt[2*9*CC];         // [g][p][c]

// ---------------------------------------------------------------------------
// Kernel 1: per-(b,c) 3x3 block sums. Writes [b][p][c].
// Blocks 0..113 additionally perform prep (transpose + BN fold), hidden
// under the DRAM-bound pooling pass.
// ---------------------------------------------------------------------------
__global__ void pool_kernel(const float* __restrict__ x,
                            const float* __restrict__ w1,
                            const float* __restrict__ bn_gamma,
                            const float* __restrict__ bn_beta,
                            const float* __restrict__ bn_mean,
                            const float* __restrict__ bn_var,
                            const float* __restrict__ w2,
                            const float* __restrict__ dyn_weight) {
    int bc = blockIdx.x;

    if (bc < 114) {
        int idx = bc * 288 + threadIdx.x;
        if (idx < CC*CR) {
            int k = idx >> 6, o = idx & 63;
            float inv = bn_gamma[o] * rsqrtf(bn_var[o] + 1e-5f);
            g_w1t[idx] = w1[o * CC + k] * inv;
        }
        if (idx < CR*2*CC) {
            int k = idx >> 9, n = idx & 511;
            g_w2t[idx] = w2[n * CR + k];
        }
        if (idx < 2*9*CC) {
            int g = idx / (9*CC);
            int rem = idx - g * 9 * CC;
            int p = rem >> 8, c = rem & 255;
            g_dwt[idx] = dyn_weight[(g * CC + c) * 9 + p];
        }
        if (idx < CR) {
            float inv = bn_gamma[idx] * rsqrtf(bn_var[idx] + 1e-5f);
            g_bnb[idx] = bn_beta[idx] - bn_mean[idx] * inv;
        }
    }

    int w = threadIdx.x >> 5;
    int lane = threadIdx.x & 31;
    int cy = w / 3, cx = w % 3;
    const float* base = x + (size_t)bc * (HH*WW) + cy * 32 * WW + cx * 32;
    float s = 0.f;
#pragma unroll
    for (int i = 0; i < 8; i++) {
        int f = lane + i * 32;
        int row = f >> 3, c4 = f & 7;
        float4 v = __ldcs(reinterpret_cast<const float4*>(base + row * WW + c4 * 4));
        s += v.x + v.y + v.z + v.w;
    }
#pragma unroll
    for (int o = 16; o; o >>= 1) s += __shfl_xor_sync(0xffffffffu, s, o);
    if (lane == 0)
        g_pooled[((bc >> 8) * 9 + w) * CC + (bc & 255)] = s;
}

// ---------------------------------------------------------------------------
// Kernel 2: fused proj. Grid (5, B) = 160 blocks; block handles positions
// p and p+5 of sample b.
// ---------------------------------------------------------------------------
__global__ __launch_bounds__(256) void projf_kernel(const float* __restrict__ dyn_bias,
                                                    const float* __restrict__ b2) {
    __shared__ float sv0[CC], sv1[CC];
    __shared__ float pa[2*256];
    __shared__ float sh0[CR], sh1[CR];
    int p = blockIdx.x;                   // 0..4
    int p2 = p + 5;                       // 5..9
    int b = blockIdx.y;
    int t = threadIdx.x;

    float v0 = g_pooled[(b * 9 + p) * CC + t] * (1.0f / 1024.0f);
    float v1;
    if (p2 < 9) {
        v1 = g_pooled[(b * 9 + p2) * CC + t] * (1.0f / 1024.0f);
    } else {
        float s = 0.f;
#pragma unroll
        for (int q = 0; q < 9; q++) s += g_pooled[(b * 9 + q) * CC + t];
        v1 = s * (1.0f / (HH * WW));
    }
    sv0[t] = v0; sv1[t] = v1;
    __syncthreads();

    int o = t & 63, slice = t >> 6;
    const float* w1s = g_w1t + slice * 64 * CR + o;
    const float* a0p = sv0 + slice * 64;
    const float* a1p = sv1 + slice * 64;
    float acc0 = 0.f, acc1 = 0.f;
#pragma unroll 8
    for (int k = 0; k < 64; k++) {
        float w = w1s[k * CR];
        acc0 = fmaf(w, a0p[k], acc0);
        acc1 = fmaf(w, a1p[k], acc1);
    }
    pa[t] = acc0; pa[256 + t] = acc1;
    __syncthreads();

    if (t < 128) {
        int pos = t >> 6, oo = t & 63;
        const float* pp = pa + pos * 256;
        float h = pp[oo] + pp[oo + 64] + pp[oo + 128] + pp[oo + 192] + g_bnb[oo];
        h = 0.5f * h * (1.0f + erff(h * 0.70710678118654752f));
        if (pos) sh1[oo] = h; else sh0[oo] = h;
    }
    __syncthreads();

    int c = t;
    float a0 = b2[c], a1 = b2[CC + c];
    float d0 = a0, d1 = a1;
#pragma unroll 8
    for (int k = 0; k < CR; k++) {
        float w_0 = g_w2t[k * 512 + c];
        float w_1 = g_w2t[k * 512 + CC + c];
        float h0 = sh0[k], h1 = sh1[k];
        a0 = fmaf(w_0, h0, a0); a1 = fmaf(w_1, h0, a1);
        d0 = fmaf(w_0, h1, d0); d1 = fmaf(w_1, h1, d1);
    }
    {
        float m = fmaxf(a0, a1);
        float e0 = __expf(a0 - m), e1 = __expf(a1 - m);
        float r = 1.0f / (e0 + e1);
        g_weight[(b * 9 + p) * CC + c] = e0 * r * g_dwt[p * CC + c]
                                       + e1 * r * g_dwt[(9 + p) * CC + c];
    }
    {
        float m = fmaxf(d0, d1);
        float e0 = __expf(d0 - m), e1 = __expf(d1 - m);
        float r = 1.0f / (e0 + e1);
        if (p2 < 9) {
            g_weight[(b * 9 + p2) * CC + c] = e0 * r * g_dwt[p2 * CC + c]
                                            + e1 * r * g_dwt[(9 + p2) * CC + c];
        } else {
            g_bias[b * CC + c] = e0 * r * dyn_bias[c] + e1 * r * dyn_bias[CC + c];
        }
    }
}

// ---------------------------------------------------------------------------
// Kernel 3: smem-staged per-sample depthwise 3x3 conv + bias.
// Staging via cp.async.cg (no RF pressure, L1 bypass). Weights loaded after
// the staging sync so live ranges don't overlap. 5 blocks/SM.
// ---------------------------------------------------------------------------
#define PITCH 104
__global__ __launch_bounds__(288, 5) void dwconv_kernel(const float* __restrict__ x,
                                                        float* __restrict__ y) {
    __shared__ float tile[98 * PITCH];
    int bc = blockIdx.x;
    int t = threadIdx.x;
    const float* img = x + (size_t)bc * (HH*WW);
    float* outimg = y + (size_t)bc * (HH*WW);

    // halo zeroing
    float4 z4 = make_float4(0.f,0.f,0.f,0.f);
    if (t < 26) {
        *reinterpret_cast<float4*>(&tile[t * 4]) = z4;
    } else if (t < 52) {
        *reinterpret_cast<float4*>(&tile[97 * PITCH + (t - 26) * 4]) = z4;
    } else if (t < 148) {
        tile[(t - 51) * PITCH + 3] = 0.f;
    } else if (t < 244) {
        tile[(t - 147) * PITCH + 100] = 0.f;
    }

    // stage image: 2304 x 16B cp.async, 8 per thread
#pragma unroll
    for (int i = 0; i < 8; i++) {
        int idx = t + i * 288;
        int r = idx / 24, j = idx % 24;
        unsigned smem_addr = (unsigned)__cvta_generic_to_shared(
            &tile[(r + 1) * PITCH + 4 + j * 4]);
        const float* gptr = img + r * WW + j * 4;
        asm volatile("cp.async.cg.shared.global [%0], [%1], 16;\n"
                     :: "r"(smem_addr), "l"(gptr));
    }
    asm volatile("cp.async.commit_group;\n");
    asm volatile("cp.async.wait_group 0;\n");
    __syncthreads();

    // weights after sync (no overlap with staging live ranges)
    int b = bc >> 8, c = bc & 255;
    float w0 = g_weight[(b*9+0)*CC+c], w1_ = g_weight[(b*9+1)*CC+c], w2_ = g_weight[(b*9+2)*CC+c];
    float w3 = g_weight[(b*9+3)*CC+c], w4  = g_weight[(b*9+4)*CC+c], w5  = g_weight[(b*9+5)*CC+c];
    float w6 = g_weight[(b*9+6)*CC+c], w7  = g_weight[(b*9+7)*CC+c], w8  = g_weight[(b*9+8)*CC+c];
    float bv = g_bias[bc];

    int tx = t % 24;
    int ty = t / 24;
    int x0 = tx * 4;
    int r0 = ty * 8;

    float4 aA = make_float4(0.f,0.f,0.f,0.f);
    float4 aB = make_float4(0.f,0.f,0.f,0.f);
    float4 aC = make_float4(0.f,0.f,0.f,0.f);

#pragma unroll
    for (int s = 0; s < 10; ++s) {
        const float* row = &tile[(r0 + s) * PITCH + 4 + x0];
        float4 v = *reinterpret_cast<const float4*>(row);
        float l = row[-1];
        float rr = row[4];
        float c0 = v.x, c1 = v.y, c2 = v.z, c3 = v.w;

        aA.x = fmaf(l,  w6, fmaf(c0, w7, fmaf(c1, w8, aA.x)));
        aA.y = fmaf(c0, w6, fmaf(c1, w7, fmaf(c2, w8, aA.y)));
        aA.z = fmaf(c1, w6, fmaf(c2, w7, fmaf(c3, w8, aA.z)));
        aA.w = fmaf(c2, w6, fmaf(c3, w7, fmaf(rr, w8, aA.w)));

        aB.x = fmaf(l,  w3, fmaf(c0, w4, fmaf(c1, w5, aB.x)));
        aB.y = fmaf(c0, w3, fmaf(c1, w4, fmaf(c2, w5, aB.y)));
        aB.z = fmaf(c1, w3, fmaf(c2, w4, fmaf(c3, w5, aB.z)));
        aB.w = fmaf(c2, w3, fmaf(c3, w4, fmaf(rr, w5, aB.w)));

        aC.x = fmaf(l,  w0, fmaf(c0, w1_, fmaf(c1, w2_, aC.x)));
        aC.y = fmaf(c0, w0, fmaf(c1, w1_, fmaf(c2, w2_, aC.y)));
        aC.z = fmaf(c1, w0, fmaf(c2, w1_, fmaf(c3, w2_, aC.z)));
        aC.w = fmaf(c2, w0, fmaf(c3, w1_, fmaf(rr, w2_, aC.w)));

        if (s >= 2) {
            int yo = r0 + s - 2;
            float4 o;
            o.x = aA.x + bv; o.y = aA.y + bv; o.z = aA.z + bv; o.w = aA.w + bv;
            __stcs(reinterpret_cast<float4*>(outimg + yo * WW + x0), o);
        }
        aA = aB; aB = aC;
        aC = make_float4(0.f,0.f,0.f,0.f);
    }
}

extern "C" void kernel_launch(void* const* d_in, const int* in_sizes, int n_in,
                              void* d_out, int out_size) {
    const float* x          = (const float*)d_in[0];
    const float* dyn_weight = (const float*)d_in[1];
    const float* dyn_bias   = (const float*)d_in[2];
    const float* w1         = (const float*)d_in[3];
    const float* bn_gamma   = (const float*)d_in[4];
    const float* bn_beta    = (const float*)d_in[5];
    const float* bn_mean    = (const float*)d_in[6];
    const float* bn_var     = (const float*)d_in[7];
    const float* w2         = (const float*)d_in[8];
    const float* b2         = (const float*)d_in[9];
    float* out = (float*)d_out;

    pool_kernel<<<BB*CC, 288>>>(x, w1, bn_gamma, bn_beta, bn_mean, bn_var, w2, dyn_weight);
    dim3 pg(5, BB);
    projf_kernel<<<pg, 256>>>(dyn_bias, b2);
    dwconv_kernel<<<BB*CC, 288>>>(x, out);
}